// round 11
// baseline (speedup 1.0000x reference)
#include <cuda_runtime.h>
#include <cuda_bf16.h>
#include <stdint.h>
#include <math.h>

#define P 8192
#define D 256
#define C_L2T 20.60992915555662f   // log2(e)/0.07
#define LN2F  0.6931471805599453f
#define NCTA 148
#define NITEMS 1024                // 64 row-tiles x 16 chunk-blocks (512 keys each)

// ---------------- device scratch (allocation-free) ----------------
__device__ int g_is64;
__device__ __align__(16) uint32_t g_Qh[P * 128];          // bf16x2 packed rows
// K in mma-B-fragment order: [kb(256)][kt(16)][u4(2)][lane(32)][4 u32] + pad
__device__ __align__(16) uint32_t g_Kf[256 * 4096 + 512];
// ksq in C-fragment order: [kb(256)][lane(32)][8 floats]
__device__ __align__(16) float g_ksqf[256 * 256];
__device__ float g_qsq[P];
__device__ float g_ksq[P];
__device__ float g_pm[P * 16];     // per-row, per-chunk-block-segment partial max
__device__ float g_ps[P * 16];     // partial sum
__device__ float g_pd[P];

// ---------------- smem: 2 Q buffers (128 rows x 528B each) + combine scratch ----------------
#define QBUF_BYTES 67584
#define OFF_PART   135168          // float2[4][128] = 4096B
#define SMEM_TOTAL 139264

// ---------------- PTX helpers (base-PTX only, sm_103-safe) ----------------
__device__ __forceinline__ uint32_t smem_u32(const void* p){
    uint32_t a;
    asm("{ .reg .u64 t; cvta.to.shared.u64 t, %1; cvt.u32.u64 %0, t; }" : "=r"(a) : "l"(p));
    return a;
}
__device__ __forceinline__ void cpa16(uint32_t dst, const void* src){
    asm volatile("cp.async.cg.shared.global [%0], [%1], 16;" :: "r"(dst), "l"(src));
}
#define CP_COMMIT asm volatile("cp.async.commit_group;" ::: "memory")
#define CP_WAIT0  asm volatile("cp.async.wait_group 0;" ::: "memory")

__device__ __forceinline__ void ldm_x4(uint32_t& r0, uint32_t& r1, uint32_t& r2, uint32_t& r3,
                                       uint32_t addr){
    asm volatile("ldmatrix.sync.aligned.m8n8.x4.shared.b16 {%0,%1,%2,%3}, [%4];"
                 : "=r"(r0), "=r"(r1), "=r"(r2), "=r"(r3) : "r"(addr));
}
__device__ __forceinline__ void mma_bf16(float c[4], const uint32_t a[4],
                                         uint32_t b0, uint32_t b1){
    asm volatile(
        "mma.sync.aligned.m16n8k16.row.col.f32.bf16.bf16.f32 "
        "{%0,%1,%2,%3}, {%4,%5,%6,%7}, {%8,%9}, {%0,%1,%2,%3};"
        : "+f"(c[0]), "+f"(c[1]), "+f"(c[2]), "+f"(c[3])
        : "r"(a[0]), "r"(a[1]), "r"(a[2]), "r"(a[3]), "r"(b0), "r"(b1));
}
__device__ __forceinline__ float ex2a(float x){ float y; asm("ex2.approx.f32 %0, %1;" : "=f"(y) : "f"(x)); return y; }
__device__ __forceinline__ float sqrta(float x){ float y; asm("sqrt.approx.f32 %0, %1;" : "=f"(y) : "f"(x)); return y; }
__device__ __forceinline__ uint32_t f2bf_bits(float x){
    return (uint32_t)__bfloat16_as_ushort(__float2bfloat16(x));
}

// ---------------- 1: dtype detection (int64 vs int32 map) ----------------
__global__ void detect_kernel(const int* __restrict__ m32){
    __shared__ int nz;
    if (threadIdx.x == 0) nz = 0;
    __syncthreads();
    int any = 0;
    for (int i = 1 + 2*(int)threadIdx.x; i < P; i += 2*(int)blockDim.x)
        if (m32[i] != 0) any = 1;
    if (any) atomicOr(&nz, 1);
    __syncthreads();
    if (threadIdx.x == 0) g_is64 = (nz == 0) ? 1 : 0;
}

// ---------------- 2: gather Q -> bf16 pack + qsq + ksq + partial-slot init ----------------
__global__ void prepQ_kernel(const float* __restrict__ f1, const float* __restrict__ f2,
                             const void* __restrict__ map){
    const int r = blockIdx.x, t = threadIdx.x;
    long long idx = g_is64 ? ((const long long*)map)[r]
                           : (long long)((const int*)map)[r];
    float2 q = reinterpret_cast<const float2*>(f1 + idx * (long long)D)[t];
    g_Qh[r*128 + t] = f2bf_bits(q.x) | (f2bf_bits(q.y) << 16);
    float2 k = reinterpret_cast<const float2*>(f2 + (long long)r * D)[t];
    if (t < 16){ g_pm[r*16 + t] = -INFINITY; g_ps[r*16 + t] = 0.f; }
    float qs = q.x*q.x + q.y*q.y;
    float ks = k.x*k.x + k.y*k.y;
    #pragma unroll
    for (int o = 16; o; o >>= 1){
        qs += __shfl_xor_sync(0xffffffffu, qs, o);
        ks += __shfl_xor_sync(0xffffffffu, ks, o);
    }
    __shared__ float sq[4], sk[4];
    if ((t & 31) == 0){ sq[t >> 5] = qs; sk[t >> 5] = ks; }
    __syncthreads();
    if (t == 0){
        g_qsq[r] = sq[0] + sq[1] + sq[2] + sq[3];
        g_ksq[r] = sk[0] + sk[1] + sk[2] + sk[3];
    }
}

// ---------------- 3: pack K into mma B-fragment layout + fragment-ordered ksq ----------------
// PTX m16n8k16 B fragment: lane L holds b0 = B[k=2(L%4)+{0,1}, n=L/4], b1 = same k+8.
// uint4 layout index: kb*1024 + kt*64 + u4*32 + lane ; u4 packs (nt0,nt1) then (nt2,nt3).
__global__ void prepKf_kernel(const float* __restrict__ f2){
    const int kb = blockIdx.x;
    for (int idx = threadIdx.x; idx < 4096; idx += 256){
        int kt  = idx >> 8;
        int rem = idx & 255;
        int u4  = rem >> 7;
        int lam = (rem >> 2) & 31;
        int p   = rem & 3;
        int nt  = u4*2 + (p >> 1);
        int w   = p & 1;
        int n = kb*32 + nt*8 + (lam >> 2);
        int k = kt*16 + w*8 + (lam & 3)*2;
        const float* src = f2 + (long long)n * D + k;
        g_Kf[kb*4096 + idx] = f2bf_bits(src[0]) | (f2bf_bits(src[1]) << 16);
    }
    {   // ksq fragment: [kb][lane][nt*2+j] = ksq[kb*32 + nt*8 + 2*(lane%4) + j]
        int lam = threadIdx.x >> 3, i = threadIdx.x & 7;
        int nt = i >> 1, j = i & 1;
        g_ksqf[kb*256 + threadIdx.x] = g_ksq[kb*32 + nt*8 + (lam & 3)*2 + j];
    }
}

// ---------------- Q tile loader (cooperative, cp.async) ----------------
__device__ __forceinline__ void load_q_tile(uint32_t dstbase, int rt, int tid){
    const int m0 = rt << 7;
    for (int j = tid; j < 128*32; j += 512){
        int row = j >> 5, c2 = j & 31;
        cpa16(dstbase + (uint32_t)(row*528 + c2*16), &g_Qh[(size_t)(m0+row)*128 + c2*4]);
    }
}

// ---------------- 4: main HMMA kernel — persistent, 148 CTAs ----------------
// Work item = (row_tile rt, chunk_block cb): 128 rows x 512 keys. 1024 items,
// CTA b handles contiguous [b*1024/148, (b+1)*1024/148) -> <=2 row-tile segments.
// 512 threads = 16 warps (4 rw x 4 cw); warp tile 32 rows x 32 keys; inner loop = R9.
__global__ void __launch_bounds__(512, 1) nce_main_kernel(){
    extern __shared__ __align__(16) uint8_t sm[];
    const uint32_t sb = smem_u32(sm);
    const int tid = threadIdx.x;
    const int lane = tid & 31, wid = tid >> 5;
    const int rw = wid >> 2, cw = wid & 3;
    const int g = lane >> 2, t = lane & 3;
    const int bid = blockIdx.x;

    int wi = (bid * NITEMS) / NCTA;
    const int we = ((bid + 1) * NITEMS) / NCTA;

    const uint32_t a_off = (uint32_t)((rw*32 + (lane & 15))*528 + (lane >> 4)*16);
    const uint4*  Bb = reinterpret_cast<const uint4*>(g_Kf);
    const float4* Kb = reinterpret_cast<const float4*>(g_ksqf);
    float2* part = (float2*)(sm + OFF_PART);

    int buf = 0;
    load_q_tile(sb, wi >> 4, tid);
    CP_COMMIT; CP_WAIT0;
    __syncthreads();

    while (wi < we){
        const int rt = wi >> 4;
        const int cb_start = wi & 15;
        int seg_end = (rt + 1) << 4;
        if (seg_end > we) seg_end = we;
        const int ncb = seg_end - wi;
        const bool havenext = (seg_end < we);
        if (havenext){ load_q_tile(sb + (uint32_t)(buf^1)*QBUF_BYTES, seg_end >> 4, tid); CP_COMMIT; }

        const int m0 = rt << 7;
        const int diag_kb = rt*4 + rw;
        const uint32_t a_base = sb + (uint32_t)buf*QBUF_BYTES + a_off;

        float qs[2][2];
        #pragma unroll
        for (int mt = 0; mt < 2; mt++){
            qs[mt][0] = g_qsq[m0 + rw*32 + mt*16 + g];
            qs[mt][1] = g_qsq[m0 + rw*32 + mt*16 + g + 8];
        }

        float mrun[2][2], srun[2][2];
        #pragma unroll
        for (int mt = 0; mt < 2; mt++)
            #pragma unroll
            for (int h = 0; h < 2; h++){ mrun[mt][h] = -INFINITY; srun[mt][h] = 0.f; }

        for (int it = 0; it < ncb; it++){
            const int kb0 = (cb_start + it)*16 + cw*4;

            // prime B pipeline (kt0, kt1 of first chunk of this item)
            uint4 blo[2], bhi[2];
            {
                const uint4* p0 = Bb + (size_t)kb0*1024 + lane;
                blo[0] = __ldg(p0);      bhi[0] = __ldg(p0 + 32);
                blo[1] = __ldg(p0 + 64); bhi[1] = __ldg(p0 + 96);
            }

            for (int c = 0; c < 4; c++){
                const int kb = kb0 + c;
                const uint4* bp  = Bb + (size_t)kb*1024 + lane;
                const uint4* npc = Bb + (size_t)(c < 3 ? kb + 1 : kb)*1024 + lane;

                float acc[2][4][4];
                #pragma unroll
                for (int mt = 0; mt < 2; mt++)
                    #pragma unroll
                    for (int nt = 0; nt < 4; nt++)
                        #pragma unroll
                        for (int q4 = 0; q4 < 4; q4++) acc[mt][nt][q4] = 0.f;

                #pragma unroll
                for (int kt = 0; kt < 16; kt++){
                    uint4 clo = blo[kt & 1], chi = bhi[kt & 1];
                    const uint4* np = (kt < 14) ? (bp + (kt + 2)*64) : (npc + (kt - 14)*64);
                    blo[kt & 1] = __ldg(np); bhi[kt & 1] = __ldg(np + 32);
                    uint32_t A0[4], A1[4];
                    ldm_x4(A0[0], A0[1], A0[2], A0[3], a_base + (uint32_t)(kt*32));
                    ldm_x4(A1[0], A1[1], A1[2], A1[3], a_base + (uint32_t)(16*528 + kt*32));
                    mma_bf16(acc[0][0], A0, clo.x, clo.y);
                    mma_bf16(acc[0][1], A0, clo.z, clo.w);
                    mma_bf16(acc[0][2], A0, chi.x, chi.y);
                    mma_bf16(acc[0][3], A0, chi.z, chi.w);
                    mma_bf16(acc[1][0], A1, clo.x, clo.y);
                    mma_bf16(acc[1][1], A1, clo.z, clo.w);
                    mma_bf16(acc[1][2], A1, chi.x, chi.y);
                    mma_bf16(acc[1][3], A1, chi.z, chi.w);
                }

                // ---- epilogue: per-thread online logsumexp (log2 domain) ----
                const float4* kp = Kb + (size_t)kb*64 + lane*2;
                float4 kq0 = __ldg(kp), kq1 = __ldg(kp + 1);
                float kq[8] = {kq0.x, kq0.y, kq0.z, kq0.w, kq1.x, kq1.y, kq1.z, kq1.w};
                const bool has_diag = (kb == diag_kb);
                #pragma unroll
                for (int mt = 0; mt < 2; mt++){
                    #pragma unroll
                    for (int h = 0; h < 2; h++){
                        const int rloc = rw*32 + mt*16 + g + 8*h;
                        float v[8];
                        float vmax = -INFINITY;
                        #pragma unroll
                        for (int nt = 0; nt < 4; nt++){
                            #pragma unroll
                            for (int j = 0; j < 2; j++){
                                float sq = fmaf(acc[mt][nt][h*2 + j], -2.f, qs[mt][h] + kq[nt*2 + j]);
                                float lv = -sqrta(fmaxf(sq, 0.f)) * C_L2T;
                                v[nt*2 + j] = lv;
                                vmax = fmaxf(vmax, lv);
                            }
                        }
                        if (has_diag){
                            #pragma unroll
                            for (int nt = 0; nt < 4; nt++)
                                #pragma unroll
                                for (int j = 0; j < 2; j++)
                                    if (nt*8 + 2*t + j == mt*16 + g + 8*h)
                                        g_pd[m0 + rloc] = v[nt*2 + j];
                        }
                        float s = 0.f;
                        #pragma unroll
                        for (int i2 = 0; i2 < 8; i2++) s += ex2a(v[i2] - vmax);
                        float nm = fmaxf(mrun[mt][h], vmax);
                        srun[mt][h] = srun[mt][h] * ex2a(fmaxf(mrun[mt][h] - nm, -126.f))
                                    + s * ex2a(vmax - nm);
                        mrun[mt][h] = nm;
                    }
                }
            }
        }

        // ---- segment flush: t-lane merge, then cross-cw merge, store to slot cb_start ----
        __syncthreads();   // protect part[] from previous flush's readers
        #pragma unroll
        for (int mt = 0; mt < 2; mt++){
            #pragma unroll
            for (int h = 0; h < 2; h++){
                float m = mrun[mt][h], s = srun[mt][h];
                #pragma unroll
                for (int o = 1; o <= 2; o <<= 1){
                    float mo = __shfl_xor_sync(0xffffffffu, m, o);
                    float so = __shfl_xor_sync(0xffffffffu, s, o);
                    float nm = fmaxf(m, mo);
                    s = s * ex2a(fmaxf(m - nm, -126.f)) + so * ex2a(fmaxf(mo - nm, -126.f));
                    m = nm;
                }
                if (t == 0) part[cw*128 + rw*32 + mt*16 + g + 8*h] = make_float2(m, s);
            }
        }
        __syncthreads();
        if (cw == 0){
            const int rl = rw*32 + lane;
            float2 p0 = part[0*128 + rl];
            float2 p1 = part[1*128 + rl];
            float2 p2 = part[2*128 + rl];
            float2 p3 = part[3*128 + rl];
            float m = fmaxf(fmaxf(p0.x, p1.x), fmaxf(p2.x, p3.x));
            float s = p0.y * ex2a(fmaxf(p0.x - m, -126.f)) + p1.y * ex2a(fmaxf(p1.x - m, -126.f))
                    + p2.y * ex2a(fmaxf(p2.x - m, -126.f)) + p3.y * ex2a(fmaxf(p3.x - m, -126.f));
            g_pm[(m0 + rl)*16 + cb_start] = m;
            g_ps[(m0 + rl)*16 + cb_start] = s;
        }

        if (havenext){ CP_WAIT0; __syncthreads(); buf ^= 1; }
        wi = seg_end;
    }
}

// ---------------- 5: merge slots + mean ----------------
__global__ void fin_kernel(float* __restrict__ out){
    float acc = 0.f;
    for (int r = threadIdx.x; r < P; r += 256){
        float m = -INFINITY;
        #pragma unroll
        for (int i = 0; i < 16; i++) m = fmaxf(m, g_pm[r*16 + i]);
        float s = 0.f;
        #pragma unroll
        for (int i = 0; i < 16; i++)
            s += g_ps[r*16 + i] * ex2a(fmaxf(g_pm[r*16 + i] - m, -126.f));
        acc += LN2F * (m + __log2f(s) - g_pd[r]);
    }
    #pragma unroll
    for (int o = 16; o; o >>= 1) acc += __shfl_xor_sync(0xffffffffu, acc, o);
    __shared__ float sw[8];
    if ((threadIdx.x & 31) == 0) sw[threadIdx.x >> 5] = acc;
    __syncthreads();
    if (threadIdx.x == 0){
        float tt = 0.f;
        #pragma unroll
        for (int i = 0; i < 8; i++) tt += sw[i];
        out[0] = tt / (float)P;
    }
}

extern "C" void kernel_launch(void* const* d_in, const int* in_sizes, int n_in,
                              void* d_out, int out_size){
    const float* f1  = (const float*)d_in[0];
    const float* f2  = (const float*)d_in[1];
    const void*  map = d_in[2];

    cudaFuncSetAttribute(nce_main_kernel,
                         cudaFuncAttributeMaxDynamicSharedMemorySize, SMEM_TOTAL);

    detect_kernel<<<1, 256>>>((const int*)map);        // launch 1
    prepQ_kernel<<<P, 128>>>(f1, f2, map);             // launch 2 (Q pack + qsq + ksq + init)
    prepKf_kernel<<<256, 256>>>(f2);                   // launch 3 (fragment pack)
    nce_main_kernel<<<NCTA, 512, SMEM_TOTAL>>>();      // launch 4 (ncu target)
    fin_kernel<<<1, 256>>>((float*)d_out);             // launch 5
}

// round 12
// speedup vs baseline: 1.5193x; 1.5193x over previous
#include <cuda_runtime.h>
#include <cuda_bf16.h>
#include <stdint.h>
#include <math.h>

#define P 8192
#define D 256
#define C_L2T 20.60992915555662f   // log2(e)/0.07
#define LN2F  0.6931471805599453f
#define NCTA 148
#define NITEMS 1024                // 64 row-tiles x 16 chunk-blocks (512 keys each)
#define FINB 64

// ---------------- device scratch (allocation-free) ----------------
__device__ int g_is64;
__device__ __align__(16) uint32_t g_Qh[P * 128];          // bf16x2 packed rows
// K in mma-B-fragment order: [kb(256)][kt(16)][u4(2)][lane(32)][4 u32] + pad
__device__ __align__(16) uint32_t g_Kf[256 * 4096 + 512];
// ksq in C-fragment order: [kb(256)][lane(32)][8 floats]
__device__ __align__(16) float g_ksqf[256 * 256];
__device__ float g_qsq[P];
__device__ float g_ksq[P];
__device__ __align__(16) float g_pm[P * 16];   // per-row, per-segment partial max
__device__ __align__(16) float g_ps[P * 16];   // partial sum
__device__ float g_pd[P];
__device__ float g_bsum[FINB];

// ---------------- smem: 2 Q buffers (128 rows x 528B each) + combine scratch ----------------
#define QBUF_BYTES 67584
#define OFF_PART   135168          // float2[4][128] = 4096B
#define SMEM_TOTAL 139264

// ---------------- PTX helpers (base-PTX only, sm_103-safe) ----------------
__device__ __forceinline__ uint32_t smem_u32(const void* p){
    uint32_t a;
    asm("{ .reg .u64 t; cvta.to.shared.u64 t, %1; cvt.u32.u64 %0, t; }" : "=r"(a) : "l"(p));
    return a;
}
__device__ __forceinline__ void cpa16(uint32_t dst, const void* src){
    asm volatile("cp.async.cg.shared.global [%0], [%1], 16;" :: "r"(dst), "l"(src));
}
#define CP_COMMIT asm volatile("cp.async.commit_group;" ::: "memory")
#define CP_WAIT0  asm volatile("cp.async.wait_group 0;" ::: "memory")

__device__ __forceinline__ void ldm_x4(uint32_t& r0, uint32_t& r1, uint32_t& r2, uint32_t& r3,
                                       uint32_t addr){
    asm volatile("ldmatrix.sync.aligned.m8n8.x4.shared.b16 {%0,%1,%2,%3}, [%4];"
                 : "=r"(r0), "=r"(r1), "=r"(r2), "=r"(r3) : "r"(addr));
}
__device__ __forceinline__ void mma_bf16(float c[4], const uint32_t a[4],
                                         uint32_t b0, uint32_t b1){
    asm volatile(
        "mma.sync.aligned.m16n8k16.row.col.f32.bf16.bf16.f32 "
        "{%0,%1,%2,%3}, {%4,%5,%6,%7}, {%8,%9}, {%0,%1,%2,%3};"
        : "+f"(c[0]), "+f"(c[1]), "+f"(c[2]), "+f"(c[3])
        : "r"(a[0]), "r"(a[1]), "r"(a[2]), "r"(a[3]), "r"(b0), "r"(b1));
}
__device__ __forceinline__ float ex2a(float x){ float y; asm("ex2.approx.f32 %0, %1;" : "=f"(y) : "f"(x)); return y; }
__device__ __forceinline__ float sqrta(float x){ float y; asm("sqrt.approx.f32 %0, %1;" : "=f"(y) : "f"(x)); return y; }
__device__ __forceinline__ uint32_t f2bf_bits(float x){
    return (uint32_t)__bfloat16_as_ushort(__float2bfloat16(x));
}

// ---------------- 1: dtype detection (int64 vs int32 map) ----------------
__global__ void detect_kernel(const int* __restrict__ m32){
    __shared__ int nz;
    if (threadIdx.x == 0) nz = 0;
    __syncthreads();
    int any = 0;
    for (int i = 1 + 2*(int)threadIdx.x; i < P; i += 2*(int)blockDim.x)
        if (m32[i] != 0) any = 1;
    if (any) atomicOr(&nz, 1);
    __syncthreads();
    if (threadIdx.x == 0) g_is64 = (nz == 0) ? 1 : 0;
}

// ---------------- 2: gather Q -> bf16 pack + qsq + ksq + partial-slot init ----------------
__global__ void prepQ_kernel(const float* __restrict__ f1, const float* __restrict__ f2,
                             const void* __restrict__ map){
    const int r = blockIdx.x, t = threadIdx.x;
    long long idx = g_is64 ? ((const long long*)map)[r]
                           : (long long)((const int*)map)[r];
    float2 q = reinterpret_cast<const float2*>(f1 + idx * (long long)D)[t];
    g_Qh[r*128 + t] = f2bf_bits(q.x) | (f2bf_bits(q.y) << 16);
    float2 k = reinterpret_cast<const float2*>(f2 + (long long)r * D)[t];
    if (t < 16){ g_pm[r*16 + t] = -INFINITY; g_ps[r*16 + t] = 0.f; }
    float qs = q.x*q.x + q.y*q.y;
    float ks = k.x*k.x + k.y*k.y;
    #pragma unroll
    for (int o = 16; o; o >>= 1){
        qs += __shfl_xor_sync(0xffffffffu, qs, o);
        ks += __shfl_xor_sync(0xffffffffu, ks, o);
    }
    __shared__ float sq[4], sk[4];
    if ((t & 31) == 0){ sq[t >> 5] = qs; sk[t >> 5] = ks; }
    __syncthreads();
    if (t == 0){
        g_qsq[r] = sq[0] + sq[1] + sq[2] + sq[3];
        g_ksq[r] = sk[0] + sk[1] + sk[2] + sk[3];
    }
}

// ---------------- 3: pack K into mma B-fragment layout + fragment-ordered ksq ----------------
// PTX m16n8k16 B fragment: lane L holds b0 = B[k=2(L%4)+{0,1}, n=L/4], b1 = same k+8.
// uint4 layout index: kb*1024 + kt*64 + u4*32 + lane ; u4 packs (nt0,nt1) then (nt2,nt3).
__global__ void prepKf_kernel(const float* __restrict__ f2){
    const int kb = blockIdx.x;
    for (int idx = threadIdx.x; idx < 4096; idx += 256){
        int kt  = idx >> 8;
        int rem = idx & 255;
        int u4  = rem >> 7;
        int lam = (rem >> 2) & 31;
        int p   = rem & 3;
        int nt  = u4*2 + (p >> 1);
        int w   = p & 1;
        int n = kb*32 + nt*8 + (lam >> 2);
        int k = kt*16 + w*8 + (lam & 3)*2;
        const float* src = f2 + (long long)n * D + k;
        g_Kf[kb*4096 + idx] = f2bf_bits(src[0]) | (f2bf_bits(src[1]) << 16);
    }
    {   // ksq fragment: [kb][lane][nt*2+j] = ksq[kb*32 + nt*8 + 2*(lane%4) + j]
        int lam = threadIdx.x >> 3, i = threadIdx.x & 7;
        int nt = i >> 1, j = i & 1;
        g_ksqf[kb*256 + threadIdx.x] = g_ksq[kb*32 + nt*8 + (lam & 3)*2 + j];
    }
}

// ---------------- Q tile loader (cooperative, cp.async) ----------------
__device__ __forceinline__ void load_q_tile(uint32_t dstbase, int rt, int tid){
    const int m0 = rt << 7;
    for (int j = tid; j < 128*32; j += 512){
        int row = j >> 5, c2 = j & 31;
        cpa16(dstbase + (uint32_t)(row*528 + c2*16), &g_Qh[(size_t)(m0+row)*128 + c2*4]);
    }
}

// ---------------- 4: main HMMA kernel — persistent, 148 CTAs ----------------
// Work item = (row_tile rt, chunk_block cb): 128 rows x 512 keys. 1024 items,
// CTA b handles contiguous [b*1024/148, (b+1)*1024/148) -> <=2 row-tile segments.
// 512 threads = 16 warps (4 rw x 4 cw); warp tile 32 rows x 32 keys.
__global__ void __launch_bounds__(512, 1) nce_main_kernel(){
    extern __shared__ __align__(16) uint8_t sm[];
    const uint32_t sb = smem_u32(sm);
    const int tid = threadIdx.x;
    const int lane = tid & 31, wid = tid >> 5;
    const int rw = wid >> 2, cw = wid & 3;
    const int g = lane >> 2, t = lane & 3;
    const int bid = blockIdx.x;

    int wi = (bid * NITEMS) / NCTA;
    const int we = ((bid + 1) * NITEMS) / NCTA;

    const uint32_t a_off = (uint32_t)((rw*32 + (lane & 15))*528 + (lane >> 4)*16);
    const uint4*  Bb = reinterpret_cast<const uint4*>(g_Kf);
    const float4* Kb = reinterpret_cast<const float4*>(g_ksqf);
    float2* part = (float2*)(sm + OFF_PART);

    int buf = 0;
    load_q_tile(sb, wi >> 4, tid);
    CP_COMMIT; CP_WAIT0;
    __syncthreads();

    while (wi < we){
        const int rt = wi >> 4;
        const int cb_start = wi & 15;
        int seg_end = (rt + 1) << 4;
        if (seg_end > we) seg_end = we;
        const int ncb = seg_end - wi;
        const bool havenext = (seg_end < we);
        if (havenext){ load_q_tile(sb + (uint32_t)(buf^1)*QBUF_BYTES, seg_end >> 4, tid); CP_COMMIT; }

        const int m0 = rt << 7;
        const int diag_kb = rt*4 + rw;
        const uint32_t a_base = sb + (uint32_t)buf*QBUF_BYTES + a_off;

        float qs[2][2];
        #pragma unroll
        for (int mt = 0; mt < 2; mt++){
            qs[mt][0] = g_qsq[m0 + rw*32 + mt*16 + g];
            qs[mt][1] = g_qsq[m0 + rw*32 + mt*16 + g + 8];
        }

        float mrun[2][2], srun[2][2];
        #pragma unroll
        for (int mt = 0; mt < 2; mt++)
            #pragma unroll
            for (int h = 0; h < 2; h++){ mrun[mt][h] = -INFINITY; srun[mt][h] = 0.f; }

        for (int it = 0; it < ncb; it++){
            const int kb0 = (cb_start + it)*16 + cw*4;

            // prime B pipeline (kt0, kt1 of first chunk of this item)
            uint4 blo[2], bhi[2];
            {
                const uint4* p0 = Bb + (size_t)kb0*1024 + lane;
                blo[0] = __ldg(p0);      bhi[0] = __ldg(p0 + 32);
                blo[1] = __ldg(p0 + 64); bhi[1] = __ldg(p0 + 96);
            }

            for (int c = 0; c < 4; c++){
                const int kb = kb0 + c;
                const uint4* bp  = Bb + (size_t)kb*1024 + lane;
                const uint4* npc = Bb + (size_t)(c < 3 ? kb + 1 : kb)*1024 + lane;

                float acc[2][4][4];
                #pragma unroll
                for (int mt = 0; mt < 2; mt++)
                    #pragma unroll
                    for (int nt = 0; nt < 4; nt++)
                        #pragma unroll
                        for (int q4 = 0; q4 < 4; q4++) acc[mt][nt][q4] = 0.f;

                #pragma unroll
                for (int kt = 0; kt < 16; kt++){
                    uint4 clo = blo[kt & 1], chi = bhi[kt & 1];
                    const uint4* np = (kt < 14) ? (bp + (kt + 2)*64) : (npc + (kt - 14)*64);
                    blo[kt & 1] = __ldg(np); bhi[kt & 1] = __ldg(np + 32);
                    uint32_t A0[4], A1[4];
                    ldm_x4(A0[0], A0[1], A0[2], A0[3], a_base + (uint32_t)(kt*32));
                    ldm_x4(A1[0], A1[1], A1[2], A1[3], a_base + (uint32_t)(16*528 + kt*32));
                    mma_bf16(acc[0][0], A0, clo.x, clo.y);
                    mma_bf16(acc[0][1], A0, clo.z, clo.w);
                    mma_bf16(acc[0][2], A0, chi.x, chi.y);
                    mma_bf16(acc[0][3], A0, chi.z, chi.w);
                    mma_bf16(acc[1][0], A1, clo.x, clo.y);
                    mma_bf16(acc[1][1], A1, clo.z, clo.w);
                    mma_bf16(acc[1][2], A1, chi.x, chi.y);
                    mma_bf16(acc[1][3], A1, chi.z, chi.w);
                }

                // ---- epilogue: per-thread online logsumexp (log2 domain) ----
                const float4* kp = Kb + (size_t)kb*64 + lane*2;
                float4 kq0 = __ldg(kp), kq1 = __ldg(kp + 1);
                float kq[8] = {kq0.x, kq0.y, kq0.z, kq0.w, kq1.x, kq1.y, kq1.z, kq1.w};
                const bool has_diag = (kb == diag_kb);
                #pragma unroll
                for (int mt = 0; mt < 2; mt++){
                    #pragma unroll
                    for (int h = 0; h < 2; h++){
                        const int rloc = rw*32 + mt*16 + g + 8*h;
                        float v[8];
                        float vmax = -INFINITY;
                        #pragma unroll
                        for (int nt = 0; nt < 4; nt++){
                            #pragma unroll
                            for (int j = 0; j < 2; j++){
                                float sq = fmaf(acc[mt][nt][h*2 + j], -2.f, qs[mt][h] + kq[nt*2 + j]);
                                float lv = -sqrta(fmaxf(sq, 0.f)) * C_L2T;
                                v[nt*2 + j] = lv;
                                vmax = fmaxf(vmax, lv);
                            }
                        }
                        if (has_diag){
                            #pragma unroll
                            for (int nt = 0; nt < 4; nt++)
                                #pragma unroll
                                for (int j = 0; j < 2; j++)
                                    if (nt*8 + 2*t + j == mt*16 + g + 8*h)
                                        g_pd[m0 + rloc] = v[nt*2 + j];
                        }
                        float s = 0.f;
                        #pragma unroll
                        for (int i2 = 0; i2 < 8; i2++) s += ex2a(v[i2] - vmax);
                        float nm = fmaxf(mrun[mt][h], vmax);
                        srun[mt][h] = srun[mt][h] * ex2a(fmaxf(mrun[mt][h] - nm, -126.f))
                                    + s * ex2a(vmax - nm);
                        mrun[mt][h] = nm;
                    }
                }
            }
        }

        // ---- segment flush: t-lane merge, then cross-cw merge, store to slot cb_start ----
        __syncthreads();   // protect part[] from previous flush's readers
        #pragma unroll
        for (int mt = 0; mt < 2; mt++){
            #pragma unroll
            for (int h = 0; h < 2; h++){
                float m = mrun[mt][h], s = srun[mt][h];
                #pragma unroll
                for (int o = 1; o <= 2; o <<= 1){
                    float mo = __shfl_xor_sync(0xffffffffu, m, o);
                    float so = __shfl_xor_sync(0xffffffffu, s, o);
                    float nm = fmaxf(m, mo);
                    s = s * ex2a(fmaxf(m - nm, -126.f)) + so * ex2a(fmaxf(mo - nm, -126.f));
                    m = nm;
                }
                if (t == 0) part[cw*128 + rw*32 + mt*16 + g + 8*h] = make_float2(m, s);
            }
        }
        __syncthreads();
        if (cw == 0){
            const int rl = rw*32 + lane;
            float2 p0 = part[0*128 + rl];
            float2 p1 = part[1*128 + rl];
            float2 p2 = part[2*128 + rl];
            float2 p3 = part[3*128 + rl];
            float m = fmaxf(fmaxf(p0.x, p1.x), fmaxf(p2.x, p3.x));
            float s = p0.y * ex2a(fmaxf(p0.x - m, -126.f)) + p1.y * ex2a(fmaxf(p1.x - m, -126.f))
                    + p2.y * ex2a(fmaxf(p2.x - m, -126.f)) + p3.y * ex2a(fmaxf(p3.x - m, -126.f));
            g_pm[(m0 + rl)*16 + cb_start] = m;
            g_ps[(m0 + rl)*16 + cb_start] = s;
        }

        if (havenext){ CP_WAIT0; __syncthreads(); buf ^= 1; }
        wi = seg_end;
    }
}

// ---------------- 5a: per-row loss + per-block partial sum (64 blocks) ----------------
__global__ void fin1_kernel(){
    const int r = blockIdx.x * 128 + threadIdx.x;   // 128 threads/block
    const float4* pm4 = reinterpret_cast<const float4*>(&g_pm[r*16]);
    const float4* ps4 = reinterpret_cast<const float4*>(&g_ps[r*16]);
    float m = -INFINITY;
    float4 pm[4], ps[4];
    #pragma unroll
    for (int i = 0; i < 4; i++){
        pm[i] = pm4[i]; ps[i] = ps4[i];
        m = fmaxf(m, fmaxf(fmaxf(pm[i].x, pm[i].y), fmaxf(pm[i].z, pm[i].w)));
    }
    float s = 0.f;
    #pragma unroll
    for (int i = 0; i < 4; i++){
        s += ps[i].x * ex2a(fmaxf(pm[i].x - m, -126.f));
        s += ps[i].y * ex2a(fmaxf(pm[i].y - m, -126.f));
        s += ps[i].z * ex2a(fmaxf(pm[i].z - m, -126.f));
        s += ps[i].w * ex2a(fmaxf(pm[i].w - m, -126.f));
    }
    float loss = LN2F * (m + __log2f(s) - g_pd[r]);
    #pragma unroll
    for (int o = 16; o; o >>= 1) loss += __shfl_xor_sync(0xffffffffu, loss, o);
    __shared__ float sw[4];
    if ((threadIdx.x & 31) == 0) sw[threadIdx.x >> 5] = loss;
    __syncthreads();
    if (threadIdx.x == 0) g_bsum[blockIdx.x] = sw[0] + sw[1] + sw[2] + sw[3];
}

// ---------------- 5b: final sum ----------------
__global__ void fin2_kernel(float* __restrict__ out){
    float v = (threadIdx.x < FINB) ? g_bsum[threadIdx.x] : 0.f;
    #pragma unroll
    for (int o = 16; o; o >>= 1) v += __shfl_xor_sync(0xffffffffu, v, o);
    __shared__ float sw[2];
    if ((threadIdx.x & 31) == 0) sw[threadIdx.x >> 5] = v;
    __syncthreads();
    if (threadIdx.x == 0) out[0] = (sw[0] + sw[1]) / (float)P;
}

extern "C" void kernel_launch(void* const* d_in, const int* in_sizes, int n_in,
                              void* d_out, int out_size){
    const float* f1  = (const float*)d_in[0];
    const float* f2  = (const float*)d_in[1];
    const void*  map = d_in[2];

    cudaFuncSetAttribute(nce_main_kernel,
                         cudaFuncAttributeMaxDynamicSharedMemorySize, SMEM_TOTAL);

    detect_kernel<<<1, 256>>>((const int*)map);        // launch 1
    prepQ_kernel<<<P, 128>>>(f1, f2, map);             // launch 2 (Q pack + qsq + ksq + init)
    prepKf_kernel<<<256, 256>>>(f2);                   // launch 3 (fragment pack)
    nce_main_kernel<<<NCTA, 512, SMEM_TOTAL>>>();      // launch 4 (ncu target)
    fin1_kernel<<<FINB, 128>>>();                      // launch 5 (parallel row loss)
    fin2_kernel<<<1, 64>>>((float*)d_out);             // launch 6 (final sum)
}

// round 13
// speedup vs baseline: 1.6046x; 1.0561x over previous
#include <cuda_runtime.h>
#include <cuda_bf16.h>
#include <stdint.h>
#include <math.h>

#define P 8192
#define D 256
#define C_L2T 20.60992915555662f   // log2(e)/0.07
#define LN2F  0.6931471805599453f
#define NCTA 148
#define NITEMS 1024                // 64 row-tiles x 16 chunk-blocks (512 keys each)
#define FINB 64

// ---------------- device scratch (allocation-free) ----------------
__device__ int g_is64;
__device__ __align__(16) uint32_t g_Qh[P * 128];          // bf16x2 packed rows
// K in mma-B-fragment order: [kb(256)][kt(16)][u4(2)][lane(32)][4 u32] + pad
__device__ __align__(16) uint32_t g_Kf[256 * 4096 + 512];
// ksq in C-fragment order: [kb(256)][lane(32)][8 floats]
__device__ __align__(16) float g_ksqf[256 * 256];
__device__ float g_qsq[P];
__device__ float g_ksq[P];
__device__ __align__(16) float g_pm[P * 16];   // per-row, per-segment partial max
__device__ __align__(16) float g_ps[P * 16];   // partial sum
__device__ float g_pd[P];
__device__ float g_bsum[FINB];

// ---------------- smem: 2 Q buffers (128 rows x 528B each) + combine scratch ----------------
#define QBUF_BYTES 67584
#define OFF_PART   135168          // float2[4][128] = 4096B
#define SMEM_TOTAL 139264

// ---------------- PTX helpers (base-PTX only, sm_103-safe) ----------------
__device__ __forceinline__ uint32_t smem_u32(const void* p){
    uint32_t a;
    asm("{ .reg .u64 t; cvta.to.shared.u64 t, %1; cvt.u32.u64 %0, t; }" : "=r"(a) : "l"(p));
    return a;
}
__device__ __forceinline__ void cpa16(uint32_t dst, const void* src){
    asm volatile("cp.async.cg.shared.global [%0], [%1], 16;" :: "r"(dst), "l"(src));
}
#define CP_COMMIT asm volatile("cp.async.commit_group;" ::: "memory")
#define CP_WAIT0  asm volatile("cp.async.wait_group 0;" ::: "memory")

__device__ __forceinline__ void ldm_x4(uint32_t& r0, uint32_t& r1, uint32_t& r2, uint32_t& r3,
                                       uint32_t addr){
    asm volatile("ldmatrix.sync.aligned.m8n8.x4.shared.b16 {%0,%1,%2,%3}, [%4];"
                 : "=r"(r0), "=r"(r1), "=r"(r2), "=r"(r3) : "r"(addr));
}
__device__ __forceinline__ void mma_bf16(float c[4], const uint32_t a[4],
                                         uint32_t b0, uint32_t b1){
    asm volatile(
        "mma.sync.aligned.m16n8k16.row.col.f32.bf16.bf16.f32 "
        "{%0,%1,%2,%3}, {%4,%5,%6,%7}, {%8,%9}, {%0,%1,%2,%3};"
        : "+f"(c[0]), "+f"(c[1]), "+f"(c[2]), "+f"(c[3])
        : "r"(a[0]), "r"(a[1]), "r"(a[2]), "r"(a[3]), "r"(b0), "r"(b1));
}
__device__ __forceinline__ float ex2a(float x){ float y; asm("ex2.approx.f32 %0, %1;" : "=f"(y) : "f"(x)); return y; }
__device__ __forceinline__ float sqrta(float x){ float y; asm("sqrt.approx.f32 %0, %1;" : "=f"(y) : "f"(x)); return y; }
__device__ __forceinline__ uint32_t f2bf_bits(float x){
    return (uint32_t)__bfloat16_as_ushort(__float2bfloat16(x));
}

// ---------------- phase desync: dependent-MUFU delay chain, length rw*32 (~rw*512cyc).
// Breaks the tensor/MUFU phase-lock between the 4 warps sharing an SMSP.
__device__ __forceinline__ void desync(int rw, int lane){
    float d = (float)(lane + 1) * 1e-8f;
    const int n = rw << 5;
    for (int i = 0; i < n; i++) d = ex2a(d - 2.0f);   // stays in (0, 0.3): never large
    if (d > 1e30f) g_pd[0] = d;                        // unreachable; defeats DCE
}

// ---------------- 1: dtype detection (int64 vs int32 map) ----------------
__global__ void detect_kernel(const int* __restrict__ m32){
    __shared__ int nz;
    if (threadIdx.x == 0) nz = 0;
    __syncthreads();
    int any = 0;
    for (int i = 1 + 2*(int)threadIdx.x; i < P; i += 2*(int)blockDim.x)
        if (m32[i] != 0) any = 1;
    if (any) atomicOr(&nz, 1);
    __syncthreads();
    if (threadIdx.x == 0) g_is64 = (nz == 0) ? 1 : 0;
}

// ---------------- 2: gather Q -> bf16 pack + qsq + ksq + partial-slot init ----------------
__global__ void prepQ_kernel(const float* __restrict__ f1, const float* __restrict__ f2,
                             const void* __restrict__ map){
    const int r = blockIdx.x, t = threadIdx.x;
    long long idx = g_is64 ? ((const long long*)map)[r]
                           : (long long)((const int*)map)[r];
    float2 q = reinterpret_cast<const float2*>(f1 + idx * (long long)D)[t];
    g_Qh[r*128 + t] = f2bf_bits(q.x) | (f2bf_bits(q.y) << 16);
    float2 k = reinterpret_cast<const float2*>(f2 + (long long)r * D)[t];
    if (t < 16){ g_pm[r*16 + t] = -INFINITY; g_ps[r*16 + t] = 0.f; }
    float qs = q.x*q.x + q.y*q.y;
    float ks = k.x*k.x + k.y*k.y;
    #pragma unroll
    for (int o = 16; o; o >>= 1){
        qs += __shfl_xor_sync(0xffffffffu, qs, o);
        ks += __shfl_xor_sync(0xffffffffu, ks, o);
    }
    __shared__ float sq[4], sk[4];
    if ((t & 31) == 0){ sq[t >> 5] = qs; sk[t >> 5] = ks; }
    __syncthreads();
    if (t == 0){
        g_qsq[r] = sq[0] + sq[1] + sq[2] + sq[3];
        g_ksq[r] = sk[0] + sk[1] + sk[2] + sk[3];
    }
}

// ---------------- 3: pack K into mma B-fragment layout + fragment-ordered ksq ----------------
// PTX m16n8k16 B fragment: lane L holds b0 = B[k=2(L%4)+{0,1}, n=L/4], b1 = same k+8.
// uint4 layout index: kb*1024 + kt*64 + u4*32 + lane ; u4 packs (nt0,nt1) then (nt2,nt3).
__global__ void prepKf_kernel(const float* __restrict__ f2){
    const int kb = blockIdx.x;
    for (int idx = threadIdx.x; idx < 4096; idx += 256){
        int kt  = idx >> 8;
        int rem = idx & 255;
        int u4  = rem >> 7;
        int lam = (rem >> 2) & 31;
        int p   = rem & 3;
        int nt  = u4*2 + (p >> 1);
        int w   = p & 1;
        int n = kb*32 + nt*8 + (lam >> 2);
        int k = kt*16 + w*8 + (lam & 3)*2;
        const float* src = f2 + (long long)n * D + k;
        g_Kf[kb*4096 + idx] = f2bf_bits(src[0]) | (f2bf_bits(src[1]) << 16);
    }
    {   // ksq fragment: [kb][lane][nt*2+j] = ksq[kb*32 + nt*8 + 2*(lane%4) + j]
        int lam = threadIdx.x >> 3, i = threadIdx.x & 7;
        int nt = i >> 1, j = i & 1;
        g_ksqf[kb*256 + threadIdx.x] = g_ksq[kb*32 + nt*8 + (lam & 3)*2 + j];
    }
}

// ---------------- Q tile loader (cooperative, cp.async) ----------------
__device__ __forceinline__ void load_q_tile(uint32_t dstbase, int rt, int tid){
    const int m0 = rt << 7;
    for (int j = tid; j < 128*32; j += 512){
        int row = j >> 5, c2 = j & 31;
        cpa16(dstbase + (uint32_t)(row*528 + c2*16), &g_Qh[(size_t)(m0+row)*128 + c2*4]);
    }
}

// ---------------- 4: main HMMA kernel — persistent, 148 CTAs ----------------
// Work item = (row_tile rt, chunk_block cb): 128 rows x 512 keys. 1024 items,
// CTA b handles contiguous [b*1024/148, (b+1)*1024/148) -> <=2 row-tile segments.
// 512 threads = 16 warps (4 rw x 4 cw); warp tile 32 rows x 32 keys.
// Same-SMSP warps (same cw) are phase-desynced by ~quarter-chunk so MUFU epilogue
// of one warp hides under HMMA of its siblings.
__global__ void __launch_bounds__(512, 1) nce_main_kernel(){
    extern __shared__ __align__(16) uint8_t sm[];
    const uint32_t sb = smem_u32(sm);
    const int tid = threadIdx.x;
    const int lane = tid & 31, wid = tid >> 5;
    const int rw = wid >> 2, cw = wid & 3;
    const int g = lane >> 2, t = lane & 3;
    const int bid = blockIdx.x;

    int wi = (bid * NITEMS) / NCTA;
    const int we = ((bid + 1) * NITEMS) / NCTA;

    const uint32_t a_off = (uint32_t)((rw*32 + (lane & 15))*528 + (lane >> 4)*16);
    const uint4*  Bb = reinterpret_cast<const uint4*>(g_Kf);
    const float4* Kb = reinterpret_cast<const float4*>(g_ksqf);
    float2* part = (float2*)(sm + OFF_PART);

    int buf = 0;
    load_q_tile(sb, wi >> 4, tid);
    CP_COMMIT; CP_WAIT0;
    __syncthreads();
    desync(rw, lane);

    while (wi < we){
        const int rt = wi >> 4;
        const int cb_start = wi & 15;
        int seg_end = (rt + 1) << 4;
        if (seg_end > we) seg_end = we;
        const int ncb = seg_end - wi;
        const bool havenext = (seg_end < we);
        if (havenext){ load_q_tile(sb + (uint32_t)(buf^1)*QBUF_BYTES, seg_end >> 4, tid); CP_COMMIT; }

        const int m0 = rt << 7;
        const int diag_kb = rt*4 + rw;
        const uint32_t a_base = sb + (uint32_t)buf*QBUF_BYTES + a_off;

        float qs[2][2];
        #pragma unroll
        for (int mt = 0; mt < 2; mt++){
            qs[mt][0] = g_qsq[m0 + rw*32 + mt*16 + g];
            qs[mt][1] = g_qsq[m0 + rw*32 + mt*16 + g + 8];
        }

        float mrun[2][2], srun[2][2];
        #pragma unroll
        for (int mt = 0; mt < 2; mt++)
            #pragma unroll
            for (int h = 0; h < 2; h++){ mrun[mt][h] = -INFINITY; srun[mt][h] = 0.f; }

        for (int it = 0; it < ncb; it++){
            const int kb0 = (cb_start + it)*16 + cw*4;

            // prime B pipeline (kt0, kt1 of first chunk of this item)
            uint4 blo[2], bhi[2];
            {
                const uint4* p0 = Bb + (size_t)kb0*1024 + lane;
                blo[0] = __ldg(p0);      bhi[0] = __ldg(p0 + 32);
                blo[1] = __ldg(p0 + 64); bhi[1] = __ldg(p0 + 96);
            }

            for (int c = 0; c < 4; c++){
                const int kb = kb0 + c;
                const uint4* bp  = Bb + (size_t)kb*1024 + lane;
                const uint4* npc = Bb + (size_t)(c < 3 ? kb + 1 : kb)*1024 + lane;

                float acc[2][4][4];
                #pragma unroll
                for (int mt = 0; mt < 2; mt++)
                    #pragma unroll
                    for (int nt = 0; nt < 4; nt++)
                        #pragma unroll
                        for (int q4 = 0; q4 < 4; q4++) acc[mt][nt][q4] = 0.f;

                #pragma unroll
                for (int kt = 0; kt < 16; kt++){
                    uint4 clo = blo[kt & 1], chi = bhi[kt & 1];
                    const uint4* np = (kt < 14) ? (bp + (kt + 2)*64) : (npc + (kt - 14)*64);
                    blo[kt & 1] = __ldg(np); bhi[kt & 1] = __ldg(np + 32);
                    uint32_t A0[4], A1[4];
                    ldm_x4(A0[0], A0[1], A0[2], A0[3], a_base + (uint32_t)(kt*32));
                    ldm_x4(A1[0], A1[1], A1[2], A1[3], a_base + (uint32_t)(16*528 + kt*32));
                    mma_bf16(acc[0][0], A0, clo.x, clo.y);
                    mma_bf16(acc[0][1], A0, clo.z, clo.w);
                    mma_bf16(acc[0][2], A0, chi.x, chi.y);
                    mma_bf16(acc[0][3], A0, chi.z, chi.w);
                    mma_bf16(acc[1][0], A1, clo.x, clo.y);
                    mma_bf16(acc[1][1], A1, clo.z, clo.w);
                    mma_bf16(acc[1][2], A1, chi.x, chi.y);
                    mma_bf16(acc[1][3], A1, chi.z, chi.w);
                }

                // ---- epilogue: per-thread online logsumexp (log2 domain) ----
                const float4* kp = Kb + (size_t)kb*64 + lane*2;
                float4 kq0 = __ldg(kp), kq1 = __ldg(kp + 1);
                float kq[8] = {kq0.x, kq0.y, kq0.z, kq0.w, kq1.x, kq1.y, kq1.z, kq1.w};
                const bool has_diag = (kb == diag_kb);
                #pragma unroll
                for (int mt = 0; mt < 2; mt++){
                    #pragma unroll
                    for (int h = 0; h < 2; h++){
                        const int rloc = rw*32 + mt*16 + g + 8*h;
                        float v[8];
                        float vmax = -INFINITY;
                        #pragma unroll
                        for (int nt = 0; nt < 4; nt++){
                            #pragma unroll
                            for (int j = 0; j < 2; j++){
                                float sq = fmaf(acc[mt][nt][h*2 + j], -2.f, qs[mt][h] + kq[nt*2 + j]);
                                float lv = -sqrta(fmaxf(sq, 0.f)) * C_L2T;
                                v[nt*2 + j] = lv;
                                vmax = fmaxf(vmax, lv);
                            }
                        }
                        if (has_diag){
                            #pragma unroll
                            for (int nt = 0; nt < 4; nt++)
                                #pragma unroll
                                for (int j = 0; j < 2; j++)
                                    if (nt*8 + 2*t + j == mt*16 + g + 8*h)
                                        g_pd[m0 + rloc] = v[nt*2 + j];
                        }
                        float s = 0.f;
                        #pragma unroll
                        for (int i2 = 0; i2 < 8; i2++) s += ex2a(v[i2] - vmax);
                        float nm = fmaxf(mrun[mt][h], vmax);
                        srun[mt][h] = srun[mt][h] * ex2a(fmaxf(mrun[mt][h] - nm, -126.f))
                                    + s * ex2a(vmax - nm);
                        mrun[mt][h] = nm;
                    }
                }
            }
        }

        // ---- segment flush: t-lane merge, then cross-cw merge, store to slot cb_start ----
        __syncthreads();   // protect part[] from previous flush's readers
        #pragma unroll
        for (int mt = 0; mt < 2; mt++){
            #pragma unroll
            for (int h = 0; h < 2; h++){
                float m = mrun[mt][h], s = srun[mt][h];
                #pragma unroll
                for (int o = 1; o <= 2; o <<= 1){
                    float mo = __shfl_xor_sync(0xffffffffu, m, o);
                    float so = __shfl_xor_sync(0xffffffffu, s, o);
                    float nm = fmaxf(m, mo);
                    s = s * ex2a(fmaxf(m - nm, -126.f)) + so * ex2a(fmaxf(mo - nm, -126.f));
                    m = nm;
                }
                if (t == 0) part[cw*128 + rw*32 + mt*16 + g + 8*h] = make_float2(m, s);
            }
        }
        __syncthreads();
        if (cw == 0){
            const int rl = rw*32 + lane;
            float2 p0 = part[0*128 + rl];
            float2 p1 = part[1*128 + rl];
            float2 p2 = part[2*128 + rl];
            float2 p3 = part[3*128 + rl];
            float m = fmaxf(fmaxf(p0.x, p1.x), fmaxf(p2.x, p3.x));
            float s = p0.y * ex2a(fmaxf(p0.x - m, -126.f)) + p1.y * ex2a(fmaxf(p1.x - m, -126.f))
                    + p2.y * ex2a(fmaxf(p2.x - m, -126.f)) + p3.y * ex2a(fmaxf(p3.x - m, -126.f));
            g_pm[(m0 + rl)*16 + cb_start] = m;
            g_ps[(m0 + rl)*16 + cb_start] = s;
        }

        if (havenext){ CP_WAIT0; __syncthreads(); buf ^= 1; }
        wi = seg_end;
        if (wi < we) desync(rw, lane);   // re-stagger after barrier re-lock
    }
}

// ---------------- 5a: per-row loss + per-block partial sum (64 blocks) ----------------
__global__ void fin1_kernel(){
    const int r = blockIdx.x * 128 + threadIdx.x;   // 128 threads/block
    const float4* pm4 = reinterpret_cast<const float4*>(&g_pm[r*16]);
    const float4* ps4 = reinterpret_cast<const float4*>(&g_ps[r*16]);
    float m = -INFINITY;
    float4 pm[4], ps[4];
    #pragma unroll
    for (int i = 0; i < 4; i++){
        pm[i] = pm4[i]; ps[i] = ps4[i];
        m = fmaxf(m, fmaxf(fmaxf(pm[i].x, pm[i].y), fmaxf(pm[i].z, pm[i].w)));
    }
    float s = 0.f;
    #pragma unroll
    for (int i = 0; i < 4; i++){
        s += ps[i].x * ex2a(fmaxf(pm[i].x - m, -126.f));
        s += ps[i].y * ex2a(fmaxf(pm[i].y - m, -126.f));
        s += ps[i].z * ex2a(fmaxf(pm[i].z - m, -126.f));
        s += ps[i].w * ex2a(fmaxf(pm[i].w - m, -126.f));
    }
    float loss = LN2F * (m + __log2f(s) - g_pd[r]);
    #pragma unroll
    for (int o = 16; o; o >>= 1) loss += __shfl_xor_sync(0xffffffffu, loss, o);
    __shared__ float sw[4];
    if ((threadIdx.x & 31) == 0) sw[threadIdx.x >> 5] = loss;
    __syncthreads();
    if (threadIdx.x == 0) g_bsum[blockIdx.x] = sw[0] + sw[1] + sw[2] + sw[3];
}

// ---------------- 5b: final sum ----------------
__global__ void fin2_kernel(float* __restrict__ out){
    float v = (threadIdx.x < FINB) ? g_bsum[threadIdx.x] : 0.f;
    #pragma unroll
    for (int o = 16; o; o >>= 1) v += __shfl_xor_sync(0xffffffffu, v, o);
    __shared__ float sw[2];
    if ((threadIdx.x & 31) == 0) sw[threadIdx.x >> 5] = v;
    __syncthreads();
    if (threadIdx.x == 0) out[0] = (sw[0] + sw[1]) / (float)P;
}

extern "C" void kernel_launch(void* const* d_in, const int* in_sizes, int n_in,
                              void* d_out, int out_size){
    const float* f1  = (const float*)d_in[0];
    const float* f2  = (const float*)d_in[1];
    const void*  map = d_in[2];

    cudaFuncSetAttribute(nce_main_kernel,
                         cudaFuncAttributeMaxDynamicSharedMemorySize, SMEM_TOTAL);

    detect_kernel<<<1, 256>>>((const int*)map);        // launch 1
    prepQ_kernel<<<P, 128>>>(f1, f2, map);             // launch 2 (Q pack + qsq + ksq + init)
    prepKf_kernel<<<256, 256>>>(f2);                   // launch 3 (fragment pack)
    nce_main_kernel<<<NCTA, 512, SMEM_TOTAL>>>();      // launch 4 (ncu target)
    fin1_kernel<<<FINB, 128>>>();                      // launch 5 (parallel row loss)
    fin2_kernel<<<1, 64>>>((float*)d_out);             // launch 6 (final sum)
}